// round 2
// baseline (speedup 1.0000x reference)
#include <cuda_runtime.h>
#include <math.h>

#define NM 4
#define IMG 64
#define CH 4096
#define PIX (IMG*IMG)
#define THREADS 256

// Scratch: device globals (no allocations allowed anywhere).
__device__ unsigned g_maxbits[NM];   // ordered-uint encoded running max per mult index
__device__ float    g_wdev[NM * 9];  // clamped & factor-scaled 3x3 taps
__device__ float    g_scale[NM];     // final multiplier per mult index

// Monotone float<->uint order encoding (for atomicMax on float incl. negatives)
__device__ __forceinline__ unsigned f2o(float f) {
    unsigned u = __float_as_uint(f);
    return (u & 0x80000000u) ? ~u : (u | 0x80000000u);
}
__device__ __forceinline__ float o2f(unsigned u) {
    return (u & 0x80000000u) ? __uint_as_float(u & 0x7fffffffu)
                             : __uint_as_float(~u);
}

// ---------------------------------------------------------------------------
// k_init: reset maxes, compute effective weights:
//   w_eff = clip(weight, -1, 1) * clip(weight_factor, 1, 255)
// ---------------------------------------------------------------------------
__global__ void k_init(const float* __restrict__ w, const float* __restrict__ wf) {
    int t = threadIdx.x;
    if (t < NM) {
        g_maxbits[t] = f2o(-INFINITY);
        float f = fminf(fmaxf(wf[t], 1.f), 255.f);
#pragma unroll
        for (int j = 0; j < 9; j++) {
            float v = fminf(fmaxf(w[t * 9 + j], -1.f), 1.f);
            g_wdev[t * 9 + j] = v * f;
        }
    }
}

// ---------------------------------------------------------------------------
// k_pass1: depthwise 3x3 conv per image, track global max per mult index.
// One block per 64x64 image. Zero-padded 66x66 smem tile (no per-tap branches).
// ---------------------------------------------------------------------------
__global__ __launch_bounds__(THREADS) void k_pass1(const float* __restrict__ in) {
    __shared__ float tile[66][66];
    int c = blockIdx.x, t = threadIdx.x;
    const float* img = in + (size_t)c * PIX;

    for (int i = t; i < 66 * 66; i += THREADS) {
        int ys = i / 66, xs = i % 66;
        float v = 0.f;
        if (ys > 0 && ys < 65 && xs > 0 && xs < 65)
            v = img[(ys - 1) * IMG + (xs - 1)];
        tile[ys][xs] = v;
    }

    float w[NM * 9];
#pragma unroll
    for (int j = 0; j < NM * 9; j++) w[j] = g_wdev[j];
    __syncthreads();

    float mx[NM];
#pragma unroll
    for (int n = 0; n < NM; n++) mx[n] = -INFINITY;

#pragma unroll
    for (int k = 0; k < PIX / THREADS; k++) {
        int p = t + k * THREADS;
        int y = p >> 6, x = p & 63;
        float p00 = tile[y][x],     p01 = tile[y][x + 1],     p02 = tile[y][x + 2];
        float p10 = tile[y + 1][x], p11 = tile[y + 1][x + 1], p12 = tile[y + 1][x + 2];
        float p20 = tile[y + 2][x], p21 = tile[y + 2][x + 1], p22 = tile[y + 2][x + 2];
#pragma unroll
        for (int n = 0; n < NM; n++) {
            float a = p00 * w[n * 9 + 0] + p01 * w[n * 9 + 1] + p02 * w[n * 9 + 2]
                    + p10 * w[n * 9 + 3] + p11 * w[n * 9 + 4] + p12 * w[n * 9 + 5]
                    + p20 * w[n * 9 + 6] + p21 * w[n * 9 + 7] + p22 * w[n * 9 + 8];
            mx[n] = fmaxf(mx[n], a);
        }
    }

    // warp reduce
#pragma unroll
    for (int n = 0; n < NM; n++)
#pragma unroll
        for (int o = 16; o; o >>= 1)
            mx[n] = fmaxf(mx[n], __shfl_xor_sync(0xffffffffu, mx[n], o));

    // block reduce -> ONE atomic per (block, n): 16K total RED ops, low contention
    __shared__ float red[NM][8];
    int warp = t >> 5, lane = t & 31;
    if (lane == 0) {
#pragma unroll
        for (int n = 0; n < NM; n++) red[n][warp] = mx[n];
    }
    __syncthreads();
    if (t < NM) {
        float m = red[t][0];
#pragma unroll
        for (int wi = 1; wi < 8; wi++) m = fmaxf(m, red[t][wi]);
        atomicMax(&g_maxbits[t], f2o(m));   // no return use -> REDG
    }
}

// ---------------------------------------------------------------------------
// k_scale: scale_n = 2^(-round(log2(max/128))) if max/128 > 0 else 1.
// Multiplying by an exact power of two == reference's divide by exp2(shift).
// ---------------------------------------------------------------------------
__global__ void k_scale() {
    int n = threadIdx.x;
    if (n < NM) {
        float m = o2f(g_maxbits[n]);
        float div = m * (1.f / 128.f);
        float s = 1.f;
        if (div > 0.f) s = exp2f(-rintf(log2f(div)));
        g_scale[n] = s;
    }
}

// ---------------------------------------------------------------------------
// k_pass2: recompute conv, apply scale, add residual, write all 4 outputs.
// out[n][0][c][y][x] = input[c][y][x] + scale_n * conv_n[c][y][x]
// ---------------------------------------------------------------------------
__global__ __launch_bounds__(THREADS) void k_pass2(const float* __restrict__ in,
                                                   float* __restrict__ out) {
    __shared__ float tile[66][66];
    int c = blockIdx.x, t = threadIdx.x;
    const float* img = in + (size_t)c * PIX;

    for (int i = t; i < 66 * 66; i += THREADS) {
        int ys = i / 66, xs = i % 66;
        float v = 0.f;
        if (ys > 0 && ys < 65 && xs > 0 && xs < 65)
            v = img[(ys - 1) * IMG + (xs - 1)];
        tile[ys][xs] = v;
    }

    float w[NM * 9], s[NM];
#pragma unroll
    for (int j = 0; j < NM * 9; j++) w[j] = g_wdev[j];
#pragma unroll
    for (int n = 0; n < NM; n++) s[n] = g_scale[n];
    __syncthreads();

    size_t cbase = (size_t)c * PIX;
#pragma unroll
    for (int k = 0; k < PIX / THREADS; k++) {
        int p = t + k * THREADS;
        int y = p >> 6, x = p & 63;
        float p00 = tile[y][x],     p01 = tile[y][x + 1],     p02 = tile[y][x + 2];
        float p10 = tile[y + 1][x], p11 = tile[y + 1][x + 1], p12 = tile[y + 1][x + 2];
        float p20 = tile[y + 2][x], p21 = tile[y + 2][x + 1], p22 = tile[y + 2][x + 2];
        float inv = p11;  // center pixel == input value
#pragma unroll
        for (int n = 0; n < NM; n++) {
            float a = p00 * w[n * 9 + 0] + p01 * w[n * 9 + 1] + p02 * w[n * 9 + 2]
                    + p10 * w[n * 9 + 3] + p11 * w[n * 9 + 4] + p12 * w[n * 9 + 5]
                    + p20 * w[n * 9 + 6] + p21 * w[n * 9 + 7] + p22 * w[n * 9 + 8];
            out[(size_t)n * CH * PIX + cbase + p] = inv + s[n] * a;
        }
    }
}

// ---------------------------------------------------------------------------
extern "C" void kernel_launch(void* const* d_in, const int* in_sizes, int n_in,
                              void* d_out, int out_size) {
    const float* in  = (const float*)d_in[0];   // [1, 4096, 64, 64]
    const float* w   = (const float*)d_in[1];   // [4, 9]
    const float* wf  = (const float*)d_in[2];   // [4, 1]
    float* out = (float*)d_out;                 // [4, 1, 4096, 64, 64]

    k_init <<<1, 32>>>(w, wf);
    k_pass1<<<CH, THREADS>>>(in);
    k_scale<<<1, 32>>>();
    k_pass2<<<CH, THREADS>>>(in, out);
}

// round 3
// speedup vs baseline: 1.5206x; 1.5206x over previous
#include <cuda_runtime.h>
#include <math.h>

#define NM 4
#define IMG 64
#define CH 4096
#define PIX (IMG*IMG)
#define THREADS 256
#define TROW 68   // padded tile row stride (floats); 68*4B = 272B = 17*16 -> rows 16B aligned

// Scratch: device globals (no allocations allowed anywhere).
__device__ unsigned g_maxbits[NM];
__device__ float    g_wdev[NM * 9];
__device__ float    g_scale[NM];

// Monotone float<->uint order encoding (atomicMax on float incl. negatives)
__device__ __forceinline__ unsigned f2o(float f) {
    unsigned u = __float_as_uint(f);
    return (u & 0x80000000u) ? ~u : (u | 0x80000000u);
}
__device__ __forceinline__ float o2f(unsigned u) {
    return (u & 0x80000000u) ? __uint_as_float(u & 0x7fffffffu)
                             : __uint_as_float(~u);
}

// Packed f32x2 helpers (FFMA2 reachable only via PTX on sm_103a)
__device__ __forceinline__ unsigned long long pk2(float a, float b) {
    unsigned long long r;
    asm("mov.b64 %0, {%1, %2};" : "=l"(r) : "f"(a), "f"(b));
    return r;
}
__device__ __forceinline__ void upk2(unsigned long long v, float& a, float& b) {
    asm("mov.b64 {%0, %1}, %2;" : "=f"(a), "=f"(b) : "l"(v));
}
__device__ __forceinline__ unsigned long long fma2(unsigned long long a,
                                                   unsigned long long b,
                                                   unsigned long long c) {
    unsigned long long d;
    asm("fma.rn.f32x2 %0, %1, %2, %3;" : "=l"(d) : "l"(a), "l"(b), "l"(c));
    return d;
}

// ---------------------------------------------------------------------------
__global__ void k_init(const float* __restrict__ w, const float* __restrict__ wf) {
    int t = threadIdx.x;
    if (t < NM) {
        g_maxbits[t] = f2o(-INFINITY);
        float f = fminf(fmaxf(wf[t], 1.f), 255.f);
#pragma unroll
        for (int j = 0; j < 9; j++) {
            float v = fminf(fmaxf(w[t * 9 + j], -1.f), 1.f);
            g_wdev[t * 9 + j] = v * f;
        }
    }
}

// ---------------------------------------------------------------------------
// Shared tile fill: zero whole padded tile, then vectorized interior fill.
__device__ __forceinline__ void fill_tile(float* tile, const float* __restrict__ img, int t) {
    for (int i = t; i < 66 * TROW; i += THREADS) tile[i] = 0.f;
    __syncthreads();
    for (int i = t; i < PIX / 4; i += THREADS) {           // 1024 float4 loads
        int row = i >> 4, c4 = (i & 15) << 2;
        float4 v = *(const float4*)(img + row * IMG + c4); // LDG.128, coalesced
        float* d = &tile[(row + 1) * TROW + 1 + c4];
        d[0] = v.x; d[1] = v.y; d[2] = v.z; d[3] = v.w;
    }
}

// ---------------------------------------------------------------------------
// Pass 1: depthwise 3x3 conv, global max per mult index. Packed f32x2 FMA:
// each thread computes 4 consecutive x-pixels as 2 packed pairs; 5 packs per
// row feed both pairs. 18 FFMA2 + 15 packs per 4 pixels (vs 36 FFMA scalar).
__global__ __launch_bounds__(THREADS) void k_pass1(const float* __restrict__ in) {
    __shared__ float tile[66 * TROW];
    int c = blockIdx.x, t = threadIdx.x;
    fill_tile(tile, in + (size_t)c * PIX, t);

    unsigned long long wp[NM * 9];
#pragma unroll
    for (int j = 0; j < NM * 9; j++) { float w = g_wdev[j]; wp[j] = pk2(w, w); }
    __syncthreads();

    float mx[NM];
#pragma unroll
    for (int n = 0; n < NM; n++) mx[n] = -INFINITY;

#pragma unroll
    for (int it = 0; it < 4; it++) {
        int y  = (t >> 4) + (it << 4);   // output row
        int x0 = (t & 15) << 2;          // first of 4 output cols (16B aligned in tile)
        const float* base = &tile[y * TROW + x0];

        unsigned long long accA[NM], accB[NM];
#pragma unroll
        for (int n = 0; n < NM; n++) { accA[n] = 0ull; accB[n] = 0ull; }

#pragma unroll
        for (int r = 0; r < 3; r++) {
            float4 v = *(const float4*)(base + r * TROW);       // LDS.128
            float2 u = *(const float2*)(base + r * TROW + 4);   // LDS.64
            unsigned long long P0 = pk2(v.x, v.y), P1 = pk2(v.y, v.z),
                               P2 = pk2(v.z, v.w), P3 = pk2(v.w, u.x),
                               P4 = pk2(u.x, u.y);
#pragma unroll
            for (int n = 0; n < NM; n++) {
                accA[n] = fma2(P0, wp[n * 9 + 3 * r + 0], accA[n]);
                accA[n] = fma2(P1, wp[n * 9 + 3 * r + 1], accA[n]);
                accA[n] = fma2(P2, wp[n * 9 + 3 * r + 2], accA[n]);
                accB[n] = fma2(P2, wp[n * 9 + 3 * r + 0], accB[n]);
                accB[n] = fma2(P3, wp[n * 9 + 3 * r + 1], accB[n]);
                accB[n] = fma2(P4, wp[n * 9 + 3 * r + 2], accB[n]);
            }
        }
#pragma unroll
        for (int n = 0; n < NM; n++) {
            float a0, a1, b0, b1;
            upk2(accA[n], a0, a1); upk2(accB[n], b0, b1);
            mx[n] = fmaxf(mx[n], fmaxf(fmaxf(a0, a1), fmaxf(b0, b1)));
        }
    }

    // warp reduce
#pragma unroll
    for (int n = 0; n < NM; n++)
#pragma unroll
        for (int o = 16; o; o >>= 1)
            mx[n] = fmaxf(mx[n], __shfl_xor_sync(0xffffffffu, mx[n], o));

    __shared__ float red[NM][8];
    int warp = t >> 5, lane = t & 31;
    if (lane == 0) {
#pragma unroll
        for (int n = 0; n < NM; n++) red[n][warp] = mx[n];
    }
    __syncthreads();
    if (t < NM) {
        float m = red[t][0];
#pragma unroll
        for (int wi = 1; wi < 8; wi++) m = fmaxf(m, red[t][wi]);
        atomicMax(&g_maxbits[t], f2o(m));   // one REDG per (block, n)
    }
}

// ---------------------------------------------------------------------------
__global__ void k_scale() {
    int n = threadIdx.x;
    if (n < NM) {
        float m = o2f(g_maxbits[n]);
        float div = m * (1.f / 128.f);
        float s = 1.f;
        if (div > 0.f) s = exp2f(-rintf(log2f(div)));   // exact power of two
        g_scale[n] = s;
    }
}

// ---------------------------------------------------------------------------
// Pass 2: recompute conv (scalar FMA, same tap order), scale + residual,
// float4 stores. 4 STG.128 per 4 pixels (vs 16 STG.32 before).
__global__ __launch_bounds__(THREADS) void k_pass2(const float* __restrict__ in,
                                                   float* __restrict__ out) {
    __shared__ float tile[66 * TROW];
    int c = blockIdx.x, t = threadIdx.x;
    fill_tile(tile, in + (size_t)c * PIX, t);

    float w[NM * 9], s[NM];
#pragma unroll
    for (int j = 0; j < NM * 9; j++) w[j] = g_wdev[j];
#pragma unroll
    for (int n = 0; n < NM; n++) s[n] = g_scale[n];
    __syncthreads();

    size_t cbase = (size_t)c * PIX;
#pragma unroll
    for (int it = 0; it < 4; it++) {
        int y  = (t >> 4) + (it << 4);
        int x0 = (t & 15) << 2;
        const float* base = &tile[y * TROW + x0];

        float rv[3][6];
#pragma unroll
        for (int r = 0; r < 3; r++) {
            float4 v = *(const float4*)(base + r * TROW);
            float2 u = *(const float2*)(base + r * TROW + 4);
            rv[r][0] = v.x; rv[r][1] = v.y; rv[r][2] = v.z;
            rv[r][3] = v.w; rv[r][4] = u.x; rv[r][5] = u.y;
        }

        size_t obase = cbase + (size_t)y * IMG + x0;
#pragma unroll
        for (int n = 0; n < NM; n++) {
            float o[4];
#pragma unroll
            for (int k = 0; k < 4; k++) {
                float a = 0.f;
#pragma unroll
                for (int r = 0; r < 3; r++) {
                    a = fmaf(rv[r][k + 0], w[n * 9 + 3 * r + 0], a);
                    a = fmaf(rv[r][k + 1], w[n * 9 + 3 * r + 1], a);
                    a = fmaf(rv[r][k + 2], w[n * 9 + 3 * r + 2], a);
                }
                o[k] = fmaf(s[n], a, rv[1][k + 1]);  // in + s*a (s = 2^k, exact)
            }
            *(float4*)(out + (size_t)n * CH * PIX + obase) =
                make_float4(o[0], o[1], o[2], o[3]);   // STG.128, coalesced
        }
    }
}

// ---------------------------------------------------------------------------
extern "C" void kernel_launch(void* const* d_in, const int* in_sizes, int n_in,
                              void* d_out, int out_size) {
    const float* in = (const float*)d_in[0];   // [1, 4096, 64, 64]
    const float* w  = (const float*)d_in[1];   // [4, 9]
    const float* wf = (const float*)d_in[2];   // [4, 1]
    float* out = (float*)d_out;                // [4, 1, 4096, 64, 64]

    k_init <<<1, 32>>>(w, wf);
    k_pass1<<<CH, THREADS>>>(in);
    k_scale<<<1, 32>>>();
    k_pass2<<<CH, THREADS>>>(in, out);
}